// round 15
// baseline (speedup 1.0000x reference)
#include <cuda_runtime.h>
#include <cuda_bf16.h>
#include <cuda_fp16.h>
#include <cstdint>

// ---------------------------------------------------------------------------
// CrossAttention. R15: occupancy experiment on gemm_out only — NSTAGE=3 +
// __launch_bounds__(128,3) => 3 CTAs/SM (12 warps vs 8). gemm_proj / attn /
// split byte-identical to validated R14 (222.1us).
// ---------------------------------------------------------------------------

#define B_SZ   32
#define N_SZ   1536
#define M_SZ   80
#define HEADS  8
#define CDIM   64
#define INNER  512
#define QD     320
#define KD     768
#define ROWS_Q (B_SZ * N_SZ)     // 49152
#define ROWS_K (B_SZ * M_SZ)     // 2560
#define SCALE  0.125f
#define LAMDA1 5.0f
#define BIGNEG (-3.402823466e38f)

// ---------------- scratch (device globals; allocation forbidden) -----------
__device__ __half g_xh[ROWS_Q * QD];
__device__ __half g_kh[ROWS_K * KD];
__device__ __half g_vh[ROWS_K * KD];
__device__ __half g_wqh[INNER * QD];
__device__ __half g_wkh[INNER * KD];
__device__ __half g_wvh[INNER * KD];
__device__ __half g_woh[QD * INNER];
__device__ __half g_q [ROWS_Q * INNER];
__device__ __half g_kp[ROWS_K * INNER];
__device__ __half g_vt[ROWS_K * INNER];   // [bh][c][m]
__device__ __half g_ao[ROWS_Q * INNER];

// ---------------------------------------------------------------------------
// primitives
// ---------------------------------------------------------------------------
__device__ __forceinline__ uint32_t smem_u32(const void* p) {
    uint32_t a;
    asm("{ .reg .u64 t; cvta.to.shared.u64 t, %1; cvt.u32.u64 %0, t; }"
        : "=r"(a) : "l"(p));
    return a;
}
__device__ __forceinline__ void cp_async16(uint32_t dst, const void* src, uint32_t sz) {
    asm volatile("cp.async.cg.shared.global [%0], [%1], 16, %2;"
                 :: "r"(dst), "l"(src), "r"(sz));
}
__device__ __forceinline__ void cp_commit() { asm volatile("cp.async.commit_group;"); }
template <int N>
__device__ __forceinline__ void cp_wait() {
    asm volatile("cp.async.wait_group %0;" :: "n"(N));
}
__device__ __forceinline__ void ldmatrix_x4(uint32_t* r, uint32_t addr) {
    asm volatile("ldmatrix.sync.aligned.m8n8.x4.shared.b16 {%0,%1,%2,%3}, [%4];"
                 : "=r"(r[0]), "=r"(r[1]), "=r"(r[2]), "=r"(r[3]) : "r"(addr));
}
__device__ __forceinline__ void ldmatrix_x2(uint32_t* r, uint32_t addr) {
    asm volatile("ldmatrix.sync.aligned.m8n8.x2.shared.b16 {%0,%1}, [%2];"
                 : "=r"(r[0]), "=r"(r[1]) : "r"(addr));
}
__device__ __forceinline__ void mma16816h(float* d, const uint32_t* a, const uint32_t* b) {
    asm volatile(
        "mma.sync.aligned.m16n8k16.row.col.f32.f16.f16.f32 "
        "{%0,%1,%2,%3}, {%4,%5,%6,%7}, {%8,%9}, {%0,%1,%2,%3};"
        : "+f"(d[0]), "+f"(d[1]), "+f"(d[2]), "+f"(d[3])
        : "r"(a[0]), "r"(a[1]), "r"(a[2]), "r"(a[3]), "r"(b[0]), "r"(b[1]));
}
__device__ __forceinline__ void h_store2(__half* dst, size_t idx, float a, float b) {
    *(__half2*)(dst + idx) = __floats2half2_rn(a, b);
}
#define SWZ(off) ((off) ^ (((off) >> 3) & 0x70))

// ---------------------------------------------------------------------------
// mega-split: all 7 fp32 tensors -> fp16; 8 floats/thread, one 16B store.
// ---------------------------------------------------------------------------
#define N8_X   (ROWS_Q * QD / 8)
#define N8_KEY (ROWS_K * KD / 8)
#define N8_VAL (ROWS_K * KD / 8)
#define N8_WQ  (INNER * QD / 8)
#define N8_WK  (INNER * KD / 8)
#define N8_WV  (INNER * KD / 8)
#define N8_WO  (QD * INNER / 8)
#define S1 (N8_X)
#define S2 (S1 + N8_KEY)
#define S3 (S2 + N8_VAL)
#define S4 (S3 + N8_WQ)
#define S5 (S4 + N8_WK)
#define S6 (S5 + N8_WV)
#define S7 (S6 + N8_WO)

__global__ void __launch_bounds__(256)
split_all(const float* __restrict__ x,   const float* __restrict__ key,
          const float* __restrict__ val, const float* __restrict__ wq,
          const float* __restrict__ wk,  const float* __restrict__ wv,
          const float* __restrict__ wo,
          __half* __restrict__ xh, __half* __restrict__ kh, __half* __restrict__ vh,
          __half* __restrict__ wqh, __half* __restrict__ wkh,
          __half* __restrict__ wvh, __half* __restrict__ woh)
{
    const int i = blockIdx.x * blockDim.x + threadIdx.x;
    if (i >= S7) return;

    const float* src; __half* dst; int off;
    if      (i < S1) { src = x;   dst = xh;  off = i;      }
    else if (i < S2) { src = key; dst = kh;  off = i - S1; }
    else if (i < S3) { src = val; dst = vh;  off = i - S2; }
    else if (i < S4) { src = wq;  dst = wqh; off = i - S3; }
    else if (i < S5) { src = wk;  dst = wkh; off = i - S4; }
    else if (i < S6) { src = wv;  dst = wvh; off = i - S5; }
    else             { src = wo;  dst = woh; off = i - S6; }

    const float4 v0 = ((const float4*)src)[(size_t)off * 2];
    const float4 v1 = ((const float4*)src)[(size_t)off * 2 + 1];
    __half2 h[4];
    h[0] = __floats2half2_rn(v0.x, v0.y);
    h[1] = __floats2half2_rn(v0.z, v0.w);
    h[2] = __floats2half2_rn(v1.x, v1.y);
    h[3] = __floats2half2_rn(v1.z, v1.w);
    ((uint4*)dst)[off] = *(const uint4*)h;
}

// ---------------------------------------------------------------------------
// fp16 1-pass GEMM core (BM=BN=128, BK=32, 4 warps 2x2, 64x64 warp tiles,
// NS-stage cp.async, single barrier per iter). NS is a template parameter:
// preload NS-1 stages, wait<NS-2>, prefetch it+NS-1.
// ---------------------------------------------------------------------------
#define STAGE_B (128 * 40 * 2)
#define KCHUNK  32

struct GemmCore {
    uint32_t sbase;
    int tid, wid, lane, wm, wn;
    int g, r8, a_row_off, a_k_off, bx_row_off, bx_k_off;

    __device__ __forceinline__ void init(uint32_t sb, int t) {
        sbase = sb; tid = t;
        wid = t >> 5; lane = t & 31;
        wm = wid >> 1; wn = wid & 1;
        g = lane >> 3; r8 = lane & 7;
        a_row_off = (g & 1) * 8 + r8;
        a_k_off   = (g >> 1) * 16;
        bx_row_off = (g >> 1) * 8 + r8;
        bx_k_off   = (g & 1) * 16;
    }

    template <bool GUARD>
    __device__ __forceinline__ void load_stage(
        const __half* A, const __half* B,
        int rbase, int cbase, int cols, int K, int it, int stage)
    {
        const int kb = it * KCHUNK;
        const uint32_t abase = sbase + stage * 2 * STAGE_B;
        const uint32_t bbase = abase + STAGE_B;
#pragma unroll
        for (int t = 0; t < 4; t++) {
            const int task = t * 128 + tid;
            const int row  = task >> 2;
            const int ch   = task & 3;
            cp_async16(abase + row * 80 + ch * 16,
                       A + (size_t)(rbase + row) * K + kb + ch * 8, 16);
        }
#pragma unroll
        for (int t = 0; t < 4; t++) {
            const int task = t * 128 + tid;
            const int row  = task >> 2;
            const int ch   = task & 3;
            if (GUARD) {
                const int col   = cbase + row;
                const int valid = (col < cols);
                cp_async16(bbase + row * 80 + ch * 16,
                           B + (size_t)(valid ? col : 0) * K + kb + ch * 8,
                           valid ? 16u : 0u);
            } else {
                cp_async16(bbase + row * 80 + ch * 16,
                           B + (size_t)(cbase + row) * K + kb + ch * 8, 16);
            }
        }
        cp_commit();
    }

    template <bool GUARD, int NS>
    __device__ __forceinline__ void run(
        float acc[4][8][4],
        const __half* A, const __half* B,
        int rbase, int cbase, int cols, int K, bool wactive = true)
    {
        const int KT = K / KCHUNK;
        load_stage<GUARD>(A, B, rbase, cbase, cols, K, 0, 0);
        load_stage<GUARD>(A, B, rbase, cbase, cols, K, 1, 1);
        if (NS >= 4)
            load_stage<GUARD>(A, B, rbase, cbase, cols, K, 2, 2);

        for (int it = 0; it < KT; it++) {
            cp_wait<NS - 2>();
            __syncthreads();
            if (it + NS - 1 < KT)
                load_stage<GUARD>(A, B, rbase, cbase, cols, K,
                                  it + NS - 1, (it + NS - 1) % NS);
            else cp_commit();

            const int stage = it % NS;
            const uint32_t sA = sbase + stage * 2 * STAGE_B;
            const uint32_t sB = sA + STAGE_B;
            if (wactive) {
#pragma unroll
                for (int s = 0; s < 2; s++) {
                    uint32_t afrag[4][4];
                    uint32_t bfrag[8][2];
#pragma unroll
                    for (int i = 0; i < 4; i++)
                        ldmatrix_x4(afrag[i],
                            sA + (wm * 64 + i * 16 + a_row_off) * 80 + s * 32 + a_k_off);
#pragma unroll
                    for (int jj = 0; jj < 4; jj++) {
                        uint32_t r[4];
                        ldmatrix_x4(r,
                            sB + (wn * 64 + jj * 16 + bx_row_off) * 80 + s * 32 + bx_k_off);
                        bfrag[jj * 2][0]     = r[0]; bfrag[jj * 2][1]     = r[1];
                        bfrag[jj * 2 + 1][0] = r[2]; bfrag[jj * 2 + 1][1] = r[3];
                    }
#pragma unroll
                    for (int i = 0; i < 4; i++)
#pragma unroll
                        for (int j = 0; j < 8; j++)
                            mma16816h(acc[i][j], afrag[i], bfrag[j]);
                }
            }
        }
    }
};

// ---------------------------------------------------------------------------
// merged projection kernel, flattened grid (4, 424). NS=4, 2 CTAs/SM
// (validated config, unchanged).
// ---------------------------------------------------------------------------
#define YQ 384
#define YK (YQ + ROWS_K / 128)    // 404
#define YV (YK + ROWS_K / 128)    // 424

__global__ void __launch_bounds__(128, 2)
gemm_proj(const __half* __restrict__ xh, const __half* __restrict__ kh,
          const __half* __restrict__ vh,
          const __half* __restrict__ wqh, const __half* __restrict__ wkh,
          const __half* __restrict__ wvh,
          __half* __restrict__ q, __half* __restrict__ kp, __half* __restrict__ vt)
{
    const int y = blockIdx.y;
    int z, ytile;
    if (y < YQ)      { z = 0; ytile = y; }
    else if (y < YK) { z = 1; ytile = y - YQ; }
    else             { z = 2; ytile = y - YK; }

    const __half *A, *B;
    __half* C;
    int K;
    float ascale = 1.0f;
    if (z == 0)      { A = xh; B = wqh; C = q;  K = QD; ascale = SCALE; }
    else if (z == 1) { A = kh; B = wkh; C = kp; K = KD; }
    else             { A = vh; B = wvh; C = vt; K = KD; }

    extern __shared__ char smem[];
    GemmCore core;
    core.init(smem_u32(smem), threadIdx.x);

    const int rbase = ytile * 128;
    const int cbase = blockIdx.x * 128;

    float acc[4][8][4];
#pragma unroll
    for (int i = 0; i < 4; i++)
#pragma unroll
        for (int j = 0; j < 8; j++)
#pragma unroll
            for (int e = 0; e < 4; e++) acc[i][j][e] = 0.0f;

    core.run<false, 4>(acc, A, B, rbase, cbase, INNER, K);

    const int qrow = core.lane >> 2;
    const int qcol = (core.lane & 3) * 2;
    if (z < 2) {
#pragma unroll
        for (int i = 0; i < 4; i++) {
            const int row0 = rbase + core.wm * 64 + i * 16 + qrow;
#pragma unroll
            for (int j = 0; j < 8; j++) {
                const int col0 = cbase + core.wn * 64 + j * 8 + qcol;
                h_store2(C, (size_t)row0 * INNER + col0,
                         acc[i][j][0] * ascale, acc[i][j][1] * ascale);
                h_store2(C, (size_t)(row0 + 8) * INNER + col0,
                         acc[i][j][2] * ascale, acc[i][j][3] * ascale);
            }
        }
    } else {
#pragma unroll
        for (int i = 0; i < 4; i++) {
            const int row0 = rbase + core.wm * 64 + i * 16 + qrow;
#pragma unroll
            for (int j = 0; j < 8; j++) {
                const int col0 = cbase + core.wn * 64 + j * 8 + qcol;
#pragma unroll
                for (int rr = 0; rr < 2; rr++) {
                    const int r = row0 + rr * 8;
                    const int bb = r / M_SZ;
                    const int m  = r - bb * M_SZ;
#pragma unroll
                    for (int cc = 0; cc < 2; cc++) {
                        const int col = col0 + cc;
                        const int idx = (bb * HEADS + (col >> 6)) * CDIM + (col & 63);
                        C[(size_t)idx * M_SZ + m] =
                            __float2half_rn(acc[i][j][rr * 2 + cc]);
                    }
                }
            }
        }
    }
}

// ---------------------------------------------------------------------------
// output projection: NS=3, 3 CTAs/SM occupancy experiment.
// grid (rows/128, 3) — light col tile (y=2) last; wn=1 warps gated there.
// ---------------------------------------------------------------------------
__global__ void __launch_bounds__(128, 3)
gemm_out(const __half* __restrict__ A, const __half* __restrict__ B,
         const float* __restrict__ bias, float* __restrict__ Cf)
{
    extern __shared__ char smem[];
    GemmCore core;
    core.init(smem_u32(smem), threadIdx.x);

    const int rbase = blockIdx.x * 128;
    const int cbase = blockIdx.y * 128;
    const bool wactive = (cbase + core.wn * 64) < QD;

    float acc[4][8][4];
#pragma unroll
    for (int i = 0; i < 4; i++)
#pragma unroll
        for (int j = 0; j < 8; j++)
#pragma unroll
            for (int e = 0; e < 4; e++) acc[i][j][e] = 0.0f;

    core.run<true, 3>(acc, A, B, rbase, cbase, QD, INNER, wactive);

    if (!wactive) return;
    const int qrow = core.lane >> 2;
    const int qcol = (core.lane & 3) * 2;
#pragma unroll
    for (int i = 0; i < 4; i++) {
        const int row0 = rbase + core.wm * 64 + i * 16 + qrow;
#pragma unroll
        for (int j = 0; j < 8; j++) {
            const int col0 = cbase + core.wn * 64 + j * 8 + qcol;
            if (col0 >= QD) continue;
            const float b0 = bias[col0], b1 = bias[col0 + 1];
            *(float2*)(Cf + (size_t)row0 * QD + col0) =
                make_float2(acc[i][j][0] + b0, acc[i][j][1] + b1);
            *(float2*)(Cf + (size_t)(row0 + 8) * QD + col0) =
                make_float2(acc[i][j][2] + b0, acc[i][j][3] + b1);
        }
    }
}

// ---------------------------------------------------------------------------
// Fused attention (R10 math, 3 CTAs/SM) — unchanged from R14.
// ---------------------------------------------------------------------------
#define AT_Q    0
#define AT_K    16384
#define AT_BOX  26624
#define AT_RED  67584
#define AT_MASK 69632
#define AT_V    0
#define AT_P    16384
#define AT_SMEM 69952

__global__ void __launch_bounds__(128, 3)
attn_fused(const __half* __restrict__ q, const __half* __restrict__ kp,
           const __half* __restrict__ vt,
           const int* __restrict__ mask, const float* __restrict__ box,
           __half* __restrict__ ao)
{
    extern __shared__ char smem[];
    const uint32_t sbase = smem_u32(smem);
    const int tid  = threadIdx.x;
    const int wid  = tid >> 5;
    const int lane = tid & 31;
    const int wr   = wid >> 1;
    const int wc   = wid & 1;
    const int bh   = blockIdx.y;
    const int b    = bh >> 3, h = bh & 7;
    const int nbase = blockIdx.x * 128;

    int* smask = (int*)(smem + AT_MASK);
    if (tid < M_SZ) smask[tid] = mask[b * M_SZ + tid];

#pragma unroll
    for (int u = 0; u < 8; u++) {
        const int task = u * 128 + tid;
        const int row  = task >> 3, ch = task & 7;
        cp_async16(sbase + AT_Q + SWZ(row * 128 + ch * 16),
                   q + (size_t)(b * N_SZ + nbase + row) * INNER + h * CDIM + ch * 8, 16);
    }
#pragma unroll
    for (int u = 0; u < 5; u++) {
        const int task = u * 128 + tid;
        const int row  = task >> 3, ch = task & 7;
        cp_async16(sbase + AT_K + SWZ(row * 128 + ch * 16),
                   kp + (size_t)(b * M_SZ + row) * INNER + h * CDIM + ch * 8, 16);
    }
#pragma unroll
    for (int u = 0; u < 20; u++) {
        const int task = u * 128 + tid;
        const int row  = task / 20, ch = task - row * 20;
        cp_async16(sbase + AT_BOX + row * 320 + ch * 16,
                   box + (size_t)(b * N_SZ + nbase + row) * M_SZ + ch * 4, 16);
    }
    cp_commit();
    cp_wait<0>();
    __syncthreads();

    const int g  = lane >> 3;
    const int r8 = lane & 7;
    const int a_row_off = (g & 1) * 8 + r8;
    const int a_k_off   = (g >> 1) * 16;

    float acc[4][5][4];
#pragma unroll
    for (int i = 0; i < 4; i++)
#pragma unroll
        for (int j = 0; j < 5; j++)
#pragma unroll
            for (int e = 0; e < 4; e++) acc[i][j][e] = 0.0f;

#pragma unroll
    for (int ks = 0; ks < 4; ks++) {
        uint32_t af[4][4], bf[5][2];
#pragma unroll
        for (int i = 0; i < 4; i++)
            ldmatrix_x4(af[i], sbase + AT_Q + SWZ((wr * 64 + i * 16 + a_row_off) * 128
                                                  + ks * 32 + a_k_off));
#pragma unroll
        for (int j = 0; j < 5; j++)
            ldmatrix_x2(bf[j], sbase + AT_K + SWZ((wc * 40 + j * 8 + r8) * 128
                                                  + ks * 32 + (g & 1) * 16));
#pragma unroll
        for (int i = 0; i < 4; i++)
#pragma unroll
            for (int j = 0; j < 5; j++)
                mma16816h(acc[i][j], af[i], bf[j]);
    }
    __syncthreads();

#pragma unroll
    for (int u = 0; u < 5; u++) {
        const int task = u * 128 + tid;
        const int row  = task / 10, ch = task - row * 10;
        cp_async16(sbase + AT_V + row * 176 + ch * 16,
                   vt + ((size_t)bh * CDIM + row) * M_SZ + ch * 8, 16);
    }
    cp_commit();

    const float* boxS = (const float*)(smem + AT_BOX);
    const int qrow = lane >> 2;
    const int qcol = (lane & 3) * 2;
#pragma unroll
    for (int i = 0; i < 4; i++)
#pragma unroll
        for (int j = 0; j < 5; j++)
#pragma unroll
            for (int e = 0; e < 4; e++) {
                const int r = wr * 64 + i * 16 + qrow + (e >> 1) * 8;
                const int c = wc * 40 + j * 8 + qcol + (e & 1);
                acc[i][j][e] = smask[c]
                    ? acc[i][j][e] + LAMDA1 * boxS[r * 80 + c] : BIGNEG;
            }

    float* rmax = (float*)(smem + AT_RED);
    float* rsum = rmax + 256;
    float rm[4][2];
#pragma unroll
    for (int i = 0; i < 4; i++)
#pragma unroll
        for (int hf = 0; hf < 2; hf++) {
            float m = BIGNEG;
#pragma unroll
            for (int j = 0; j < 5; j++)
                m = fmaxf(m, fmaxf(acc[i][j][hf * 2], acc[i][j][hf * 2 + 1]));
            m = fmaxf(m, __shfl_xor_sync(0xffffffffu, m, 1));
            m = fmaxf(m, __shfl_xor_sync(0xffffffffu, m, 2));
            rm[i][hf] = m;
        }
    if ((lane & 3) == 0)
#pragma unroll
        for (int i = 0; i < 4; i++)
#pragma unroll
            for (int hf = 0; hf < 2; hf++)
                rmax[wc * 128 + wr * 64 + i * 16 + qrow + hf * 8] = rm[i][hf];
    __syncthreads();

    float rs[4][2];
#pragma unroll
    for (int i = 0; i < 4; i++)
#pragma unroll
        for (int hf = 0; hf < 2; hf++) {
            const int r = wr * 64 + i * 16 + qrow + hf * 8;
            const float m = fmaxf(rmax[r], rmax[128 + r]);
            float s = 0.0f;
#pragma unroll
            for (int j = 0; j < 5; j++) {
                acc[i][j][hf * 2]     = __expf(acc[i][j][hf * 2]     - m);
                acc[i][j][hf * 2 + 1] = __expf(acc[i][j][hf * 2 + 1] - m);
                s += acc[i][j][hf * 2] + acc[i][j][hf * 2 + 1];
            }
            s += __shfl_xor_sync(0xffffffffu, s, 1);
            s += __shfl_xor_sync(0xffffffffu, s, 2);
            rs[i][hf] = s;
        }
    if ((lane & 3) == 0)
#pragma unroll
        for (int i = 0; i < 4; i++)
#pragma unroll
            for (int hf = 0; hf < 2; hf++)
                rsum[wc * 128 + wr * 64 + i * 16 + qrow + hf * 8] = rs[i][hf];
    __syncthreads();

#pragma unroll
    for (int i = 0; i < 4; i++)
#pragma unroll
        for (int hf = 0; hf < 2; hf++) {
            const int r = wr * 64 + i * 16 + qrow + hf * 8;
            const float inv = 1.0f / (rsum[r] + rsum[128 + r]);
#pragma unroll
            for (int j = 0; j < 5; j++) {
                const int c0 = wc * 40 + j * 8 + qcol;
                *(__half2*)(smem + AT_P + r * 176 + c0 * 2) =
                    __floats2half2_rn(acc[i][j][hf * 2] * inv,
                                      acc[i][j][hf * 2 + 1] * inv);
            }
        }
    cp_wait<0>();
    __syncthreads();

    float acc2[4][4][4];
#pragma unroll
    for (int i = 0; i < 4; i++)
#pragma unroll
        for (int j = 0; j < 4; j++)
#pragma unroll
            for (int e = 0; e < 4; e++) acc2[i][j][e] = 0.0f;

#pragma unroll
    for (int ks = 0; ks < 5; ks++) {
        uint32_t af[4][4], bf[4][2];
#pragma unroll
        for (int i = 0; i < 4; i++)
            ldmatrix_x4(af[i], sbase + AT_P + (wr * 64 + i * 16 + a_row_off) * 176
                                  + ks * 32 + a_k_off);
#pragma unroll
        for (int j = 0; j < 4; j++)
            ldmatrix_x2(bf[j], sbase + AT_V + (wc * 32 + j * 8 + r8) * 176
                                  + ks * 32 + (g & 1) * 16);
#pragma unroll
        for (int i = 0; i < 4; i++)
#pragma unroll
            for (int j = 0; j < 4; j++)
                mma16816h(acc2[i][j], af[i], bf[j]);
    }

#pragma unroll
    for (int i = 0; i < 4; i++) {
        const int n0 = nbase + wr * 64 + i * 16 + qrow;
#pragma unroll
        for (int j = 0; j < 4; j++) {
            const int c0 = wc * 32 + j * 8 + qcol;
            const size_t i0 = (size_t)(b * N_SZ + n0) * INNER + h * CDIM + c0;
            *(__half2*)(ao + i0) =
                __floats2half2_rn(acc2[i][j][0], acc2[i][j][1]);
            *(__half2*)(ao + i0 + (size_t)8 * INNER) =
                __floats2half2_rn(acc2[i][j][2], acc2[i][j][3]);
        }
    }
}

// ---------------------------------------------------------------------------
// Launch (4 kernels total)
// ---------------------------------------------------------------------------
extern "C" void kernel_launch(void* const* d_in, const int* in_sizes, int n_in,
                              void* d_out, int out_size)
{
    const float* x    = (const float*)d_in[0];
    const float* key  = (const float*)d_in[1];
    const float* val  = (const float*)d_in[2];
    const int*   mask = (const int*)d_in[3];
    const float* box  = (const float*)d_in[4];
    // d_in[5] road map: softmax-invariant, unused
    const float* Wq   = (const float*)d_in[6];
    const float* Wk   = (const float*)d_in[7];
    const float* Wv   = (const float*)d_in[8];
    const float* Wo   = (const float*)d_in[9];
    const float* bo   = (const float*)d_in[10];
    float*       out  = (float*)d_out;

    __half *xh, *kh, *vh, *wqh, *wkh, *wvh, *woh, *q, *kp, *vt, *ao;
    cudaGetSymbolAddress((void**)&xh, g_xh);
    cudaGetSymbolAddress((void**)&kh, g_kh);
    cudaGetSymbolAddress((void**)&vh, g_vh);
    cudaGetSymbolAddress((void**)&wqh, g_wqh);
    cudaGetSymbolAddress((void**)&wkh, g_wkh);
    cudaGetSymbolAddress((void**)&wvh, g_wvh);
    cudaGetSymbolAddress((void**)&woh, g_woh);
    cudaGetSymbolAddress((void**)&q,  g_q);
    cudaGetSymbolAddress((void**)&kp, g_kp);
    cudaGetSymbolAddress((void**)&vt, g_vt);
    cudaGetSymbolAddress((void**)&ao, g_ao);

    constexpr int SMEM_P = 4 * 2 * STAGE_B;   // 81920 (proj, NS=4)
    constexpr int SMEM_O = 3 * 2 * STAGE_B;   // 61440 (out, NS=3)
    cudaFuncSetAttribute(gemm_proj, cudaFuncAttributeMaxDynamicSharedMemorySize, SMEM_P);
    cudaFuncSetAttribute(gemm_out,  cudaFuncAttributeMaxDynamicSharedMemorySize, SMEM_O);
    cudaFuncSetAttribute(attn_fused, cudaFuncAttributeMaxDynamicSharedMemorySize, AT_SMEM);

    // 1) all fp32 -> fp16 conversions
    split_all<<<(S7 + 255) / 256, 256>>>(
        x, key, val, Wq, Wk, Wv, Wo, xh, kh, vh, wqh, wkh, wvh, woh);

    // 2) projections, flattened grid (NS=4, 2 CTAs/SM, validated)
    gemm_proj<<<dim3(INNER / 128, YV), 128, SMEM_P>>>(
        xh, kh, vh, wqh, wkh, wvh, q, kp, vt);

    // 3) fused attention (3 CTAs/SM)
    attn_fused<<<dim3(N_SZ / 128, B_SZ * HEADS), 128, AT_SMEM>>>(
        q, kp, vt, mask, box, ao);

    // 4) output projection + bias (NS=3, 3 CTAs/SM experiment)
    gemm_out<<<dim3(ROWS_Q / 128, (QD + 127) / 128), 128, SMEM_O>>>(
        ao, woh, bo, out);
}

// round 16
// speedup vs baseline: 1.0020x; 1.0020x over previous
#include <cuda_runtime.h>
#include <cuda_bf16.h>
#include <cuda_fp16.h>
#include <cstdint>

// ---------------------------------------------------------------------------
// CrossAttention. R16: gemm_out reverted to validated R14 config (NS=4,
// 2 CTAs/SM — the 3-CTA experiment lost to reg spills). Attention: softmax
// max-subtraction removed (scores bounded, exp fits fp32; saves a reduction
// + one __syncthreads). Everything else identical to R14 (222.1us).
// ---------------------------------------------------------------------------

#define B_SZ   32
#define N_SZ   1536
#define M_SZ   80
#define HEADS  8
#define CDIM   64
#define INNER  512
#define QD     320
#define KD     768
#define ROWS_Q (B_SZ * N_SZ)     // 49152
#define ROWS_K (B_SZ * M_SZ)     // 2560
#define SCALE  0.125f
#define LAMDA1 5.0f
#define BIGNEG (-3.402823466e38f)

// ---------------- scratch (device globals; allocation forbidden) -----------
__device__ __half g_xh[ROWS_Q * QD];
__device__ __half g_kh[ROWS_K * KD];
__device__ __half g_vh[ROWS_K * KD];
__device__ __half g_wqh[INNER * QD];
__device__ __half g_wkh[INNER * KD];
__device__ __half g_wvh[INNER * KD];
__device__ __half g_woh[QD * INNER];
__device__ __half g_q [ROWS_Q * INNER];
__device__ __half g_kp[ROWS_K * INNER];
__device__ __half g_vt[ROWS_K * INNER];   // [bh][c][m]
__device__ __half g_ao[ROWS_Q * INNER];

// ---------------------------------------------------------------------------
// primitives
// ---------------------------------------------------------------------------
__device__ __forceinline__ uint32_t smem_u32(const void* p) {
    uint32_t a;
    asm("{ .reg .u64 t; cvta.to.shared.u64 t, %1; cvt.u32.u64 %0, t; }"
        : "=r"(a) : "l"(p));
    return a;
}
__device__ __forceinline__ void cp_async16(uint32_t dst, const void* src, uint32_t sz) {
    asm volatile("cp.async.cg.shared.global [%0], [%1], 16, %2;"
                 :: "r"(dst), "l"(src), "r"(sz));
}
__device__ __forceinline__ void cp_commit() { asm volatile("cp.async.commit_group;"); }
template <int N>
__device__ __forceinline__ void cp_wait() {
    asm volatile("cp.async.wait_group %0;" :: "n"(N));
}
__device__ __forceinline__ void ldmatrix_x4(uint32_t* r, uint32_t addr) {
    asm volatile("ldmatrix.sync.aligned.m8n8.x4.shared.b16 {%0,%1,%2,%3}, [%4];"
                 : "=r"(r[0]), "=r"(r[1]), "=r"(r[2]), "=r"(r[3]) : "r"(addr));
}
__device__ __forceinline__ void ldmatrix_x2(uint32_t* r, uint32_t addr) {
    asm volatile("ldmatrix.sync.aligned.m8n8.x2.shared.b16 {%0,%1}, [%2];"
                 : "=r"(r[0]), "=r"(r[1]) : "r"(addr));
}
__device__ __forceinline__ void mma16816h(float* d, const uint32_t* a, const uint32_t* b) {
    asm volatile(
        "mma.sync.aligned.m16n8k16.row.col.f32.f16.f16.f32 "
        "{%0,%1,%2,%3}, {%4,%5,%6,%7}, {%8,%9}, {%0,%1,%2,%3};"
        : "+f"(d[0]), "+f"(d[1]), "+f"(d[2]), "+f"(d[3])
        : "r"(a[0]), "r"(a[1]), "r"(a[2]), "r"(a[3]), "r"(b[0]), "r"(b[1]));
}
__device__ __forceinline__ void h_store2(__half* dst, size_t idx, float a, float b) {
    *(__half2*)(dst + idx) = __floats2half2_rn(a, b);
}
#define SWZ(off) ((off) ^ (((off) >> 3) & 0x70))

// ---------------------------------------------------------------------------
// mega-split: all 7 fp32 tensors -> fp16; 8 floats/thread, one 16B store.
// ---------------------------------------------------------------------------
#define N8_X   (ROWS_Q * QD / 8)
#define N8_KEY (ROWS_K * KD / 8)
#define N8_VAL (ROWS_K * KD / 8)
#define N8_WQ  (INNER * QD / 8)
#define N8_WK  (INNER * KD / 8)
#define N8_WV  (INNER * KD / 8)
#define N8_WO  (QD * INNER / 8)
#define S1 (N8_X)
#define S2 (S1 + N8_KEY)
#define S3 (S2 + N8_VAL)
#define S4 (S3 + N8_WQ)
#define S5 (S4 + N8_WK)
#define S6 (S5 + N8_WV)
#define S7 (S6 + N8_WO)

__global__ void __launch_bounds__(256)
split_all(const float* __restrict__ x,   const float* __restrict__ key,
          const float* __restrict__ val, const float* __restrict__ wq,
          const float* __restrict__ wk,  const float* __restrict__ wv,
          const float* __restrict__ wo,
          __half* __restrict__ xh, __half* __restrict__ kh, __half* __restrict__ vh,
          __half* __restrict__ wqh, __half* __restrict__ wkh,
          __half* __restrict__ wvh, __half* __restrict__ woh)
{
    const int i = blockIdx.x * blockDim.x + threadIdx.x;
    if (i >= S7) return;

    const float* src; __half* dst; int off;
    if      (i < S1) { src = x;   dst = xh;  off = i;      }
    else if (i < S2) { src = key; dst = kh;  off = i - S1; }
    else if (i < S3) { src = val; dst = vh;  off = i - S2; }
    else if (i < S4) { src = wq;  dst = wqh; off = i - S3; }
    else if (i < S5) { src = wk;  dst = wkh; off = i - S4; }
    else if (i < S6) { src = wv;  dst = wvh; off = i - S5; }
    else             { src = wo;  dst = woh; off = i - S6; }

    const float4 v0 = ((const float4*)src)[(size_t)off * 2];
    const float4 v1 = ((const float4*)src)[(size_t)off * 2 + 1];
    __half2 h[4];
    h[0] = __floats2half2_rn(v0.x, v0.y);
    h[1] = __floats2half2_rn(v0.z, v0.w);
    h[2] = __floats2half2_rn(v1.x, v1.y);
    h[3] = __floats2half2_rn(v1.z, v1.w);
    ((uint4*)dst)[off] = *(const uint4*)h;
}

// ---------------------------------------------------------------------------
// fp16 1-pass GEMM core (BM=BN=128, BK=32, 4 warps 2x2, 64x64 warp tiles,
// 4-stage cp.async, single barrier per iter). Validated R14 config.
// ---------------------------------------------------------------------------
#define STAGE_B (128 * 40 * 2)
#define NSTAGE  4
#define KCHUNK  32

struct GemmCore {
    uint32_t sbase;
    int tid, wid, lane, wm, wn;
    int g, r8, a_row_off, a_k_off, bx_row_off, bx_k_off;

    __device__ __forceinline__ void init(uint32_t sb, int t) {
        sbase = sb; tid = t;
        wid = t >> 5; lane = t & 31;
        wm = wid >> 1; wn = wid & 1;
        g = lane >> 3; r8 = lane & 7;
        a_row_off = (g & 1) * 8 + r8;
        a_k_off   = (g >> 1) * 16;
        bx_row_off = (g >> 1) * 8 + r8;
        bx_k_off   = (g & 1) * 16;
    }

    template <bool GUARD>
    __device__ __forceinline__ void load_stage(
        const __half* A, const __half* B,
        int rbase, int cbase, int cols, int K, int it, int stage)
    {
        const int kb = it * KCHUNK;
        const uint32_t abase = sbase + stage * 2 * STAGE_B;
        const uint32_t bbase = abase + STAGE_B;
#pragma unroll
        for (int t = 0; t < 4; t++) {
            const int task = t * 128 + tid;
            const int row  = task >> 2;
            const int ch   = task & 3;
            cp_async16(abase + row * 80 + ch * 16,
                       A + (size_t)(rbase + row) * K + kb + ch * 8, 16);
        }
#pragma unroll
        for (int t = 0; t < 4; t++) {
            const int task = t * 128 + tid;
            const int row  = task >> 2;
            const int ch   = task & 3;
            if (GUARD) {
                const int col   = cbase + row;
                const int valid = (col < cols);
                cp_async16(bbase + row * 80 + ch * 16,
                           B + (size_t)(valid ? col : 0) * K + kb + ch * 8,
                           valid ? 16u : 0u);
            } else {
                cp_async16(bbase + row * 80 + ch * 16,
                           B + (size_t)(cbase + row) * K + kb + ch * 8, 16);
            }
        }
        cp_commit();
    }

    template <bool GUARD>
    __device__ __forceinline__ void run(
        float acc[4][8][4],
        const __half* A, const __half* B,
        int rbase, int cbase, int cols, int K, bool wactive = true)
    {
        const int KT = K / KCHUNK;
        load_stage<GUARD>(A, B, rbase, cbase, cols, K, 0, 0);
        load_stage<GUARD>(A, B, rbase, cbase, cols, K, 1, 1);
        load_stage<GUARD>(A, B, rbase, cbase, cols, K, 2, 2);

        for (int it = 0; it < KT; it++) {
            cp_wait<2>();
            __syncthreads();
            if (it + 3 < KT)
                load_stage<GUARD>(A, B, rbase, cbase, cols, K,
                                  it + 3, (it + 3) & (NSTAGE - 1));
            else cp_commit();

            const int stage = it & (NSTAGE - 1);
            const uint32_t sA = sbase + stage * 2 * STAGE_B;
            const uint32_t sB = sA + STAGE_B;
            if (wactive) {
#pragma unroll
                for (int s = 0; s < 2; s++) {
                    uint32_t afrag[4][4];
                    uint32_t bfrag[8][2];
#pragma unroll
                    for (int i = 0; i < 4; i++)
                        ldmatrix_x4(afrag[i],
                            sA + (wm * 64 + i * 16 + a_row_off) * 80 + s * 32 + a_k_off);
#pragma unroll
                    for (int jj = 0; jj < 4; jj++) {
                        uint32_t r[4];
                        ldmatrix_x4(r,
                            sB + (wn * 64 + jj * 16 + bx_row_off) * 80 + s * 32 + bx_k_off);
                        bfrag[jj * 2][0]     = r[0]; bfrag[jj * 2][1]     = r[1];
                        bfrag[jj * 2 + 1][0] = r[2]; bfrag[jj * 2 + 1][1] = r[3];
                    }
#pragma unroll
                    for (int i = 0; i < 4; i++)
#pragma unroll
                        for (int j = 0; j < 8; j++)
                            mma16816h(acc[i][j], afrag[i], bfrag[j]);
                }
            }
        }
    }
};

// ---------------------------------------------------------------------------
// merged projection kernel, flattened grid (4, 424).
// ---------------------------------------------------------------------------
#define YQ 384
#define YK (YQ + ROWS_K / 128)    // 404
#define YV (YK + ROWS_K / 128)    // 424

__global__ void __launch_bounds__(128, 2)
gemm_proj(const __half* __restrict__ xh, const __half* __restrict__ kh,
          const __half* __restrict__ vh,
          const __half* __restrict__ wqh, const __half* __restrict__ wkh,
          const __half* __restrict__ wvh,
          __half* __restrict__ q, __half* __restrict__ kp, __half* __restrict__ vt)
{
    const int y = blockIdx.y;
    int z, ytile;
    if (y < YQ)      { z = 0; ytile = y; }
    else if (y < YK) { z = 1; ytile = y - YQ; }
    else             { z = 2; ytile = y - YK; }

    const __half *A, *B;
    __half* C;
    int K;
    float ascale = 1.0f;
    if (z == 0)      { A = xh; B = wqh; C = q;  K = QD; ascale = SCALE; }
    else if (z == 1) { A = kh; B = wkh; C = kp; K = KD; }
    else             { A = vh; B = wvh; C = vt; K = KD; }

    extern __shared__ char smem[];
    GemmCore core;
    core.init(smem_u32(smem), threadIdx.x);

    const int rbase = ytile * 128;
    const int cbase = blockIdx.x * 128;

    float acc[4][8][4];
#pragma unroll
    for (int i = 0; i < 4; i++)
#pragma unroll
        for (int j = 0; j < 8; j++)
#pragma unroll
            for (int e = 0; e < 4; e++) acc[i][j][e] = 0.0f;

    core.run<false>(acc, A, B, rbase, cbase, INNER, K);

    const int qrow = core.lane >> 2;
    const int qcol = (core.lane & 3) * 2;
    if (z < 2) {
#pragma unroll
        for (int i = 0; i < 4; i++) {
            const int row0 = rbase + core.wm * 64 + i * 16 + qrow;
#pragma unroll
            for (int j = 0; j < 8; j++) {
                const int col0 = cbase + core.wn * 64 + j * 8 + qcol;
                h_store2(C, (size_t)row0 * INNER + col0,
                         acc[i][j][0] * ascale, acc[i][j][1] * ascale);
                h_store2(C, (size_t)(row0 + 8) * INNER + col0,
                         acc[i][j][2] * ascale, acc[i][j][3] * ascale);
            }
        }
    } else {
#pragma unroll
        for (int i = 0; i < 4; i++) {
            const int row0 = rbase + core.wm * 64 + i * 16 + qrow;
#pragma unroll
            for (int j = 0; j < 8; j++) {
                const int col0 = cbase + core.wn * 64 + j * 8 + qcol;
#pragma unroll
                for (int rr = 0; rr < 2; rr++) {
                    const int r = row0 + rr * 8;
                    const int bb = r / M_SZ;
                    const int m  = r - bb * M_SZ;
#pragma unroll
                    for (int cc = 0; cc < 2; cc++) {
                        const int col = col0 + cc;
                        const int idx = (bb * HEADS + (col >> 6)) * CDIM + (col & 63);
                        C[(size_t)idx * M_SZ + m] =
                            __float2half_rn(acc[i][j][rr * 2 + cc]);
                    }
                }
            }
        }
    }
}

// ---------------------------------------------------------------------------
// output projection (validated R14 config: NS=4, 2 CTAs/SM, light tile last)
// ---------------------------------------------------------------------------
__global__ void __launch_bounds__(128, 2)
gemm_out(const __half* __restrict__ A, const __half* __restrict__ B,
         const float* __restrict__ bias, float* __restrict__ Cf)
{
    extern __shared__ char smem[];
    GemmCore core;
    core.init(smem_u32(smem), threadIdx.x);

    const int rbase = blockIdx.x * 128;
    const int cbase = blockIdx.y * 128;
    const bool wactive = (cbase + core.wn * 64) < QD;

    float acc[4][8][4];
#pragma unroll
    for (int i = 0; i < 4; i++)
#pragma unroll
        for (int j = 0; j < 8; j++)
#pragma unroll
            for (int e = 0; e < 4; e++) acc[i][j][e] = 0.0f;

    core.run<true>(acc, A, B, rbase, cbase, QD, INNER, wactive);

    if (!wactive) return;
    const int qrow = core.lane >> 2;
    const int qcol = (core.lane & 3) * 2;
#pragma unroll
    for (int i = 0; i < 4; i++) {
        const int row0 = rbase + core.wm * 64 + i * 16 + qrow;
#pragma unroll
        for (int j = 0; j < 8; j++) {
            const int col0 = cbase + core.wn * 64 + j * 8 + qcol;
            if (col0 >= QD) continue;
            const float b0 = bias[col0], b1 = bias[col0 + 1];
            *(float2*)(Cf + (size_t)row0 * QD + col0) =
                make_float2(acc[i][j][0] + b0, acc[i][j][1] + b1);
            *(float2*)(Cf + (size_t)(row0 + 8) * QD + col0) =
                make_float2(acc[i][j][2] + b0, acc[i][j][3] + b1);
        }
    }
}

// ---------------------------------------------------------------------------
// Fused attention: softmax WITHOUT max-subtraction (scores bounded ~|30|,
// exp fits fp32; masked -> exp(-FLT_MAX) = 0). One fewer reduction + sync.
// ---------------------------------------------------------------------------
#define AT_Q    0
#define AT_K    16384
#define AT_BOX  26624
#define AT_RED  67584
#define AT_MASK 69632
#define AT_V    0
#define AT_P    16384
#define AT_SMEM 69952

__global__ void __launch_bounds__(128, 3)
attn_fused(const __half* __restrict__ q, const __half* __restrict__ kp,
           const __half* __restrict__ vt,
           const int* __restrict__ mask, const float* __restrict__ box,
           __half* __restrict__ ao)
{
    extern __shared__ char smem[];
    const uint32_t sbase = smem_u32(smem);
    const int tid  = threadIdx.x;
    const int wid  = tid >> 5;
    const int lane = tid & 31;
    const int wr   = wid >> 1;
    const int wc   = wid & 1;
    const int bh   = blockIdx.y;
    const int b    = bh >> 3, h = bh & 7;
    const int nbase = blockIdx.x * 128;

    int* smask = (int*)(smem + AT_MASK);
    if (tid < M_SZ) smask[tid] = mask[b * M_SZ + tid];

#pragma unroll
    for (int u = 0; u < 8; u++) {
        const int task = u * 128 + tid;
        const int row  = task >> 3, ch = task & 7;
        cp_async16(sbase + AT_Q + SWZ(row * 128 + ch * 16),
                   q + (size_t)(b * N_SZ + nbase + row) * INNER + h * CDIM + ch * 8, 16);
    }
#pragma unroll
    for (int u = 0; u < 5; u++) {
        const int task = u * 128 + tid;
        const int row  = task >> 3, ch = task & 7;
        cp_async16(sbase + AT_K + SWZ(row * 128 + ch * 16),
                   kp + (size_t)(b * M_SZ + row) * INNER + h * CDIM + ch * 8, 16);
    }
#pragma unroll
    for (int u = 0; u < 20; u++) {
        const int task = u * 128 + tid;
        const int row  = task / 20, ch = task - row * 20;
        cp_async16(sbase + AT_BOX + row * 320 + ch * 16,
                   box + (size_t)(b * N_SZ + nbase + row) * M_SZ + ch * 4, 16);
    }
    cp_commit();
    cp_wait<0>();
    __syncthreads();

    const int g  = lane >> 3;
    const int r8 = lane & 7;
    const int a_row_off = (g & 1) * 8 + r8;
    const int a_k_off   = (g >> 1) * 16;

    float acc[4][5][4];
#pragma unroll
    for (int i = 0; i < 4; i++)
#pragma unroll
        for (int j = 0; j < 5; j++)
#pragma unroll
            for (int e = 0; e < 4; e++) acc[i][j][e] = 0.0f;

#pragma unroll
    for (int ks = 0; ks < 4; ks++) {
        uint32_t af[4][4], bf[5][2];
#pragma unroll
        for (int i = 0; i < 4; i++)
            ldmatrix_x4(af[i], sbase + AT_Q + SWZ((wr * 64 + i * 16 + a_row_off) * 128
                                                  + ks * 32 + a_k_off));
#pragma unroll
        for (int j = 0; j < 5; j++)
            ldmatrix_x2(bf[j], sbase + AT_K + SWZ((wc * 40 + j * 8 + r8) * 128
                                                  + ks * 32 + (g & 1) * 16));
#pragma unroll
        for (int i = 0; i < 4; i++)
#pragma unroll
            for (int j = 0; j < 5; j++)
                mma16816h(acc[i][j], af[i], bf[j]);
    }
    __syncthreads();

#pragma unroll
    for (int u = 0; u < 5; u++) {
        const int task = u * 128 + tid;
        const int row  = task / 10, ch = task - row * 10;
        cp_async16(sbase + AT_V + row * 176 + ch * 16,
                   vt + ((size_t)bh * CDIM + row) * M_SZ + ch * 8, 16);
    }
    cp_commit();

    // ---- mask + box bias, exp WITHOUT max subtraction ----
    const float* boxS = (const float*)(smem + AT_BOX);
    const int qrow = lane >> 2;
    const int qcol = (lane & 3) * 2;
#pragma unroll
    for (int i = 0; i < 4; i++)
#pragma unroll
        for (int j = 0; j < 5; j++)
#pragma unroll
            for (int e = 0; e < 4; e++) {
                const int r = wr * 64 + i * 16 + qrow + (e >> 1) * 8;
                const int c = wc * 40 + j * 8 + qcol + (e & 1);
                acc[i][j][e] = smask[c]
                    ? __expf(acc[i][j][e] + LAMDA1 * boxS[r * 80 + c]) : 0.0f;
            }

    // ---- row sums (single reduction) ----
    float* rsum = (float*)(smem + AT_RED);
    float rs[4][2];
#pragma unroll
    for (int i = 0; i < 4; i++)
#pragma unroll
        for (int hf = 0; hf < 2; hf++) {
            float s = 0.0f;
#pragma unroll
            for (int j = 0; j < 5; j++)
                s += acc[i][j][hf * 2] + acc[i][j][hf * 2 + 1];
            s += __shfl_xor_sync(0xffffffffu, s, 1);
            s += __shfl_xor_sync(0xffffffffu, s, 2);
            rs[i][hf] = s;
        }
    if ((lane & 3) == 0)
#pragma unroll
        for (int i = 0; i < 4; i++)
#pragma unroll
            for (int hf = 0; hf < 2; hf++)
                rsum[wc * 128 + wr * 64 + i * 16 + qrow + hf * 8] = rs[i][hf];
    __syncthreads();

    // ---- normalize, store P fp16 ----
#pragma unroll
    for (int i = 0; i < 4; i++)
#pragma unroll
        for (int hf = 0; hf < 2; hf++) {
            const int r = wr * 64 + i * 16 + qrow + hf * 8;
            const float inv = 1.0f / (rsum[r] + rsum[128 + r]);
#pragma unroll
            for (int j = 0; j < 5; j++) {
                const int c0 = wc * 40 + j * 8 + qcol;
                *(__half2*)(smem + AT_P + r * 176 + c0 * 2) =
                    __floats2half2_rn(acc[i][j][hf * 2] * inv,
                                      acc[i][j][hf * 2 + 1] * inv);
            }
        }
    cp_wait<0>();
    __syncthreads();

    float acc2[4][4][4];
#pragma unroll
    for (int i = 0; i < 4; i++)
#pragma unroll
        for (int j = 0; j < 4; j++)
#pragma unroll
            for (int e = 0; e < 4; e++) acc2[i][j][e] = 0.0f;

#pragma unroll
    for (int ks = 0; ks < 5; ks++) {
        uint32_t af[4][4], bf[4][2];
#pragma unroll
        for (int i = 0; i < 4; i++)
            ldmatrix_x4(af[i], sbase + AT_P + (wr * 64 + i * 16 + a_row_off) * 176
                                  + ks * 32 + a_k_off);
#pragma unroll
        for (int j = 0; j < 4; j++)
            ldmatrix_x2(bf[j], sbase + AT_V + (wc * 32 + j * 8 + r8) * 176
                                  + ks * 32 + (g & 1) * 16);
#pragma unroll
        for (int i = 0; i < 4; i++)
#pragma unroll
            for (int j = 0; j < 4; j++)
                mma16816h(acc2[i][j], af[i], bf[j]);
    }

#pragma unroll
    for (int i = 0; i < 4; i++) {
        const int n0 = nbase + wr * 64 + i * 16 + qrow;
#pragma unroll
        for (int j = 0; j < 4; j++) {
            const int c0 = wc * 32 + j * 8 + qcol;
            const size_t i0 = (size_t)(b * N_SZ + n0) * INNER + h * CDIM + c0;
            *(__half2*)(ao + i0) =
                __floats2half2_rn(acc2[i][j][0], acc2[i][j][1]);
            *(__half2*)(ao + i0 + (size_t)8 * INNER) =
                __floats2half2_rn(acc2[i][j][2], acc2[i][j][3]);
        }
    }
}

// ---------------------------------------------------------------------------
// Launch (4 kernels total)
// ---------------------------------------------------------------------------
extern "C" void kernel_launch(void* const* d_in, const int* in_sizes, int n_in,
                              void* d_out, int out_size)
{
    const float* x    = (const float*)d_in[0];
    const float* key  = (const float*)d_in[1];
    const float* val  = (const float*)d_in[2];
    const int*   mask = (const int*)d_in[3];
    const float* box  = (const float*)d_in[4];
    // d_in[5] road map: softmax-invariant, unused
    const float* Wq   = (const float*)d_in[6];
    const float* Wk   = (const float*)d_in[7];
    const float* Wv   = (const float*)d_in[8];
    const float* Wo   = (const float*)d_in[9];
    const float* bo   = (const float*)d_in[10];
    float*       out  = (float*)d_out;

    __half *xh, *kh, *vh, *wqh, *wkh, *wvh, *woh, *q, *kp, *vt, *ao;
    cudaGetSymbolAddress((void**)&xh, g_xh);
    cudaGetSymbolAddress((void**)&kh, g_kh);
    cudaGetSymbolAddress((void**)&vh, g_vh);
    cudaGetSymbolAddress((void**)&wqh, g_wqh);
    cudaGetSymbolAddress((void**)&wkh, g_wkh);
    cudaGetSymbolAddress((void**)&wvh, g_wvh);
    cudaGetSymbolAddress((void**)&woh, g_woh);
    cudaGetSymbolAddress((void**)&q,  g_q);
    cudaGetSymbolAddress((void**)&kp, g_kp);
    cudaGetSymbolAddress((void**)&vt, g_vt);
    cudaGetSymbolAddress((void**)&ao, g_ao);

    constexpr int SMEM_G = NSTAGE * 2 * STAGE_B;   // 81920
    cudaFuncSetAttribute(gemm_proj, cudaFuncAttributeMaxDynamicSharedMemorySize, SMEM_G);
    cudaFuncSetAttribute(gemm_out,  cudaFuncAttributeMaxDynamicSharedMemorySize, SMEM_G);
    cudaFuncSetAttribute(attn_fused, cudaFuncAttributeMaxDynamicSharedMemorySize, AT_SMEM);

    // 1) all fp32 -> fp16 conversions
    split_all<<<(S7 + 255) / 256, 256>>>(
        x, key, val, Wq, Wk, Wv, Wo, xh, kh, vh, wqh, wkh, wvh, woh);

    // 2) projections, flattened grid
    gemm_proj<<<dim3(INNER / 128, YV), 128, SMEM_G>>>(
        xh, kh, vh, wqh, wkh, wvh, q, kp, vt);

    // 3) fused attention (no-max softmax)
    attn_fused<<<dim3(N_SZ / 128, B_SZ * HEADS), 128, AT_SMEM>>>(
        q, kp, vt, mask, box, ao);

    // 4) output projection + bias (R14 config)
    gemm_out<<<dim3(ROWS_Q / 128, (QD + 127) / 128), 128, SMEM_G>>>(
        ao, woh, bo, out);
}

// round 17
// speedup vs baseline: 1.0364x; 1.0344x over previous
#include <cuda_runtime.h>
#include <cuda_bf16.h>
#include <cuda_fp16.h>
#include <cstdint>

// ---------------------------------------------------------------------------
// CrossAttention. R17: R14 baseline restored (attention with max-subtraction,
// gemm_out NS=4/2CTA) + gemm_proj segment reorder: long K/V CTAs (K=768,
// 2.4x duration) launch FIRST, short Q CTAs fill the tail waves.
// ---------------------------------------------------------------------------

#define B_SZ   32
#define N_SZ   1536
#define M_SZ   80
#define HEADS  8
#define CDIM   64
#define INNER  512
#define QD     320
#define KD     768
#define ROWS_Q (B_SZ * N_SZ)     // 49152
#define ROWS_K (B_SZ * M_SZ)     // 2560
#define SCALE  0.125f
#define LAMDA1 5.0f
#define BIGNEG (-3.402823466e38f)

// ---------------- scratch (device globals; allocation forbidden) -----------
__device__ __half g_xh[ROWS_Q * QD];
__device__ __half g_kh[ROWS_K * KD];
__device__ __half g_vh[ROWS_K * KD];
__device__ __half g_wqh[INNER * QD];
__device__ __half g_wkh[INNER * KD];
__device__ __half g_wvh[INNER * KD];
__device__ __half g_woh[QD * INNER];
__device__ __half g_q [ROWS_Q * INNER];
__device__ __half g_kp[ROWS_K * INNER];
__device__ __half g_vt[ROWS_K * INNER];   // [bh][c][m]
__device__ __half g_ao[ROWS_Q * INNER];

// ---------------------------------------------------------------------------
// primitives
// ---------------------------------------------------------------------------
__device__ __forceinline__ uint32_t smem_u32(const void* p) {
    uint32_t a;
    asm("{ .reg .u64 t; cvta.to.shared.u64 t, %1; cvt.u32.u64 %0, t; }"
        : "=r"(a) : "l"(p));
    return a;
}
__device__ __forceinline__ void cp_async16(uint32_t dst, const void* src, uint32_t sz) {
    asm volatile("cp.async.cg.shared.global [%0], [%1], 16, %2;"
                 :: "r"(dst), "l"(src), "r"(sz));
}
__device__ __forceinline__ void cp_commit() { asm volatile("cp.async.commit_group;"); }
template <int N>
__device__ __forceinline__ void cp_wait() {
    asm volatile("cp.async.wait_group %0;" :: "n"(N));
}
__device__ __forceinline__ void ldmatrix_x4(uint32_t* r, uint32_t addr) {
    asm volatile("ldmatrix.sync.aligned.m8n8.x4.shared.b16 {%0,%1,%2,%3}, [%4];"
                 : "=r"(r[0]), "=r"(r[1]), "=r"(r[2]), "=r"(r[3]) : "r"(addr));
}
__device__ __forceinline__ void ldmatrix_x2(uint32_t* r, uint32_t addr) {
    asm volatile("ldmatrix.sync.aligned.m8n8.x2.shared.b16 {%0,%1}, [%2];"
                 : "=r"(r[0]), "=r"(r[1]) : "r"(addr));
}
__device__ __forceinline__ void mma16816h(float* d, const uint32_t* a, const uint32_t* b) {
    asm volatile(
        "mma.sync.aligned.m16n8k16.row.col.f32.f16.f16.f32 "
        "{%0,%1,%2,%3}, {%4,%5,%6,%7}, {%8,%9}, {%0,%1,%2,%3};"
        : "+f"(d[0]), "+f"(d[1]), "+f"(d[2]), "+f"(d[3])
        : "r"(a[0]), "r"(a[1]), "r"(a[2]), "r"(a[3]), "r"(b[0]), "r"(b[1]));
}
__device__ __forceinline__ void h_store2(__half* dst, size_t idx, float a, float b) {
    *(__half2*)(dst + idx) = __floats2half2_rn(a, b);
}
#define SWZ(off) ((off) ^ (((off) >> 3) & 0x70))

// ---------------------------------------------------------------------------
// mega-split: all 7 fp32 tensors -> fp16; 8 floats/thread, one 16B store.
// ---------------------------------------------------------------------------
#define N8_X   (ROWS_Q * QD / 8)
#define N8_KEY (ROWS_K * KD / 8)
#define N8_VAL (ROWS_K * KD / 8)
#define N8_WQ  (INNER * QD / 8)
#define N8_WK  (INNER * KD / 8)
#define N8_WV  (INNER * KD / 8)
#define N8_WO  (QD * INNER / 8)
#define S1 (N8_X)
#define S2 (S1 + N8_KEY)
#define S3 (S2 + N8_VAL)
#define S4 (S3 + N8_WQ)
#define S5 (S4 + N8_WK)
#define S6 (S5 + N8_WV)
#define S7 (S6 + N8_WO)

__global__ void __launch_bounds__(256)
split_all(const float* __restrict__ x,   const float* __restrict__ key,
          const float* __restrict__ val, const float* __restrict__ wq,
          const float* __restrict__ wk,  const float* __restrict__ wv,
          const float* __restrict__ wo,
          __half* __restrict__ xh, __half* __restrict__ kh, __half* __restrict__ vh,
          __half* __restrict__ wqh, __half* __restrict__ wkh,
          __half* __restrict__ wvh, __half* __restrict__ woh)
{
    const int i = blockIdx.x * blockDim.x + threadIdx.x;
    if (i >= S7) return;

    const float* src; __half* dst; int off;
    if      (i < S1) { src = x;   dst = xh;  off = i;      }
    else if (i < S2) { src = key; dst = kh;  off = i - S1; }
    else if (i < S3) { src = val; dst = vh;  off = i - S2; }
    else if (i < S4) { src = wq;  dst = wqh; off = i - S3; }
    else if (i < S5) { src = wk;  dst = wkh; off = i - S4; }
    else if (i < S6) { src = wv;  dst = wvh; off = i - S5; }
    else             { src = wo;  dst = woh; off = i - S6; }

    const float4 v0 = ((const float4*)src)[(size_t)off * 2];
    const float4 v1 = ((const float4*)src)[(size_t)off * 2 + 1];
    __half2 h[4];
    h[0] = __floats2half2_rn(v0.x, v0.y);
    h[1] = __floats2half2_rn(v0.z, v0.w);
    h[2] = __floats2half2_rn(v1.x, v1.y);
    h[3] = __floats2half2_rn(v1.z, v1.w);
    ((uint4*)dst)[off] = *(const uint4*)h;
}

// ---------------------------------------------------------------------------
// fp16 1-pass GEMM core (BM=BN=128, BK=32, 4 warps 2x2, 64x64 warp tiles,
// 4-stage cp.async, single barrier per iter). Validated R14 config.
// ---------------------------------------------------------------------------
#define STAGE_B (128 * 40 * 2)
#define NSTAGE  4
#define KCHUNK  32

struct GemmCore {
    uint32_t sbase;
    int tid, wid, lane, wm, wn;
    int g, r8, a_row_off, a_k_off, bx_row_off, bx_k_off;

    __device__ __forceinline__ void init(uint32_t sb, int t) {
        sbase = sb; tid = t;
        wid = t >> 5; lane = t & 31;
        wm = wid >> 1; wn = wid & 1;
        g = lane >> 3; r8 = lane & 7;
        a_row_off = (g & 1) * 8 + r8;
        a_k_off   = (g >> 1) * 16;
        bx_row_off = (g >> 1) * 8 + r8;
        bx_k_off   = (g & 1) * 16;
    }

    template <bool GUARD>
    __device__ __forceinline__ void load_stage(
        const __half* A, const __half* B,
        int rbase, int cbase, int cols, int K, int it, int stage)
    {
        const int kb = it * KCHUNK;
        const uint32_t abase = sbase + stage * 2 * STAGE_B;
        const uint32_t bbase = abase + STAGE_B;
#pragma unroll
        for (int t = 0; t < 4; t++) {
            const int task = t * 128 + tid;
            const int row  = task >> 2;
            const int ch   = task & 3;
            cp_async16(abase + row * 80 + ch * 16,
                       A + (size_t)(rbase + row) * K + kb + ch * 8, 16);
        }
#pragma unroll
        for (int t = 0; t < 4; t++) {
            const int task = t * 128 + tid;
            const int row  = task >> 2;
            const int ch   = task & 3;
            if (GUARD) {
                const int col   = cbase + row;
                const int valid = (col < cols);
                cp_async16(bbase + row * 80 + ch * 16,
                           B + (size_t)(valid ? col : 0) * K + kb + ch * 8,
                           valid ? 16u : 0u);
            } else {
                cp_async16(bbase + row * 80 + ch * 16,
                           B + (size_t)(cbase + row) * K + kb + ch * 8, 16);
            }
        }
        cp_commit();
    }

    template <bool GUARD>
    __device__ __forceinline__ void run(
        float acc[4][8][4],
        const __half* A, const __half* B,
        int rbase, int cbase, int cols, int K, bool wactive = true)
    {
        const int KT = K / KCHUNK;
        load_stage<GUARD>(A, B, rbase, cbase, cols, K, 0, 0);
        load_stage<GUARD>(A, B, rbase, cbase, cols, K, 1, 1);
        load_stage<GUARD>(A, B, rbase, cbase, cols, K, 2, 2);

        for (int it = 0; it < KT; it++) {
            cp_wait<2>();
            __syncthreads();
            if (it + 3 < KT)
                load_stage<GUARD>(A, B, rbase, cbase, cols, K,
                                  it + 3, (it + 3) & (NSTAGE - 1));
            else cp_commit();

            const int stage = it & (NSTAGE - 1);
            const uint32_t sA = sbase + stage * 2 * STAGE_B;
            const uint32_t sB = sA + STAGE_B;
            if (wactive) {
#pragma unroll
                for (int s = 0; s < 2; s++) {
                    uint32_t afrag[4][4];
                    uint32_t bfrag[8][2];
#pragma unroll
                    for (int i = 0; i < 4; i++)
                        ldmatrix_x4(afrag[i],
                            sA + (wm * 64 + i * 16 + a_row_off) * 80 + s * 32 + a_k_off);
#pragma unroll
                    for (int jj = 0; jj < 4; jj++) {
                        uint32_t r[4];
                        ldmatrix_x4(r,
                            sB + (wn * 64 + jj * 16 + bx_row_off) * 80 + s * 32 + bx_k_off);
                        bfrag[jj * 2][0]     = r[0]; bfrag[jj * 2][1]     = r[1];
                        bfrag[jj * 2 + 1][0] = r[2]; bfrag[jj * 2 + 1][1] = r[3];
                    }
#pragma unroll
                    for (int i = 0; i < 4; i++)
#pragma unroll
                        for (int j = 0; j < 8; j++)
                            mma16816h(acc[i][j], afrag[i], bfrag[j]);
                }
            }
        }
    }
};

// ---------------------------------------------------------------------------
// merged projection kernel, flattened grid (4, 424) — LONG CTAs FIRST:
//   y in [0, 20)    -> K tile rows (K=768, 24 iters)
//   y in [20, 40)   -> V tile rows (K=768, transposed out)
//   y in [40, 424)  -> Q tile rows (K=320, 10 iters) fill the tail
// ---------------------------------------------------------------------------
#define YSEG_K 20
#define YSEG_V 40
#define YTOT   (YSEG_V + ROWS_Q / 128)   // 424

__global__ void __launch_bounds__(128, 2)
gemm_proj(const __half* __restrict__ xh, const __half* __restrict__ kh,
          const __half* __restrict__ vh,
          const __half* __restrict__ wqh, const __half* __restrict__ wkh,
          const __half* __restrict__ wvh,
          __half* __restrict__ q, __half* __restrict__ kp, __half* __restrict__ vt)
{
    const int y = blockIdx.y;
    int z, ytile;
    if (y < YSEG_K)      { z = 1; ytile = y; }
    else if (y < YSEG_V) { z = 2; ytile = y - YSEG_K; }
    else                 { z = 0; ytile = y - YSEG_V; }

    const __half *A, *B;
    __half* C;
    int K;
    float ascale = 1.0f;
    if (z == 0)      { A = xh; B = wqh; C = q;  K = QD; ascale = SCALE; }
    else if (z == 1) { A = kh; B = wkh; C = kp; K = KD; }
    else             { A = vh; B = wvh; C = vt; K = KD; }

    extern __shared__ char smem[];
    GemmCore core;
    core.init(smem_u32(smem), threadIdx.x);

    const int rbase = ytile * 128;
    const int cbase = blockIdx.x * 128;

    float acc[4][8][4];
#pragma unroll
    for (int i = 0; i < 4; i++)
#pragma unroll
        for (int j = 0; j < 8; j++)
#pragma unroll
            for (int e = 0; e < 4; e++) acc[i][j][e] = 0.0f;

    core.run<false>(acc, A, B, rbase, cbase, INNER, K);

    const int qrow = core.lane >> 2;
    const int qcol = (core.lane & 3) * 2;
    if (z < 2) {
#pragma unroll
        for (int i = 0; i < 4; i++) {
            const int row0 = rbase + core.wm * 64 + i * 16 + qrow;
#pragma unroll
            for (int j = 0; j < 8; j++) {
                const int col0 = cbase + core.wn * 64 + j * 8 + qcol;
                h_store2(C, (size_t)row0 * INNER + col0,
                         acc[i][j][0] * ascale, acc[i][j][1] * ascale);
                h_store2(C, (size_t)(row0 + 8) * INNER + col0,
                         acc[i][j][2] * ascale, acc[i][j][3] * ascale);
            }
        }
    } else {
#pragma unroll
        for (int i = 0; i < 4; i++) {
            const int row0 = rbase + core.wm * 64 + i * 16 + qrow;
#pragma unroll
            for (int j = 0; j < 8; j++) {
                const int col0 = cbase + core.wn * 64 + j * 8 + qcol;
#pragma unroll
                for (int rr = 0; rr < 2; rr++) {
                    const int r = row0 + rr * 8;
                    const int bb = r / M_SZ;
                    const int m  = r - bb * M_SZ;
#pragma unroll
                    for (int cc = 0; cc < 2; cc++) {
                        const int col = col0 + cc;
                        const int idx = (bb * HEADS + (col >> 6)) * CDIM + (col & 63);
                        C[(size_t)idx * M_SZ + m] =
                            __float2half_rn(acc[i][j][rr * 2 + cc]);
                    }
                }
            }
        }
    }
}

// ---------------------------------------------------------------------------
// output projection (validated R14 config: NS=4, 2 CTAs/SM, light tile last)
// ---------------------------------------------------------------------------
__global__ void __launch_bounds__(128, 2)
gemm_out(const __half* __restrict__ A, const __half* __restrict__ B,
         const float* __restrict__ bias, float* __restrict__ Cf)
{
    extern __shared__ char smem[];
    GemmCore core;
    core.init(smem_u32(smem), threadIdx.x);

    const int rbase = blockIdx.x * 128;
    const int cbase = blockIdx.y * 128;
    const bool wactive = (cbase + core.wn * 64) < QD;

    float acc[4][8][4];
#pragma unroll
    for (int i = 0; i < 4; i++)
#pragma unroll
        for (int j = 0; j < 8; j++)
#pragma unroll
            for (int e = 0; e < 4; e++) acc[i][j][e] = 0.0f;

    core.run<true>(acc, A, B, rbase, cbase, QD, INNER, wactive);

    if (!wactive) return;
    const int qrow = core.lane >> 2;
    const int qcol = (core.lane & 3) * 2;
#pragma unroll
    for (int i = 0; i < 4; i++) {
        const int row0 = rbase + core.wm * 64 + i * 16 + qrow;
#pragma unroll
        for (int j = 0; j < 8; j++) {
            const int col0 = cbase + core.wn * 64 + j * 8 + qcol;
            if (col0 >= QD) continue;
            const float b0 = bias[col0], b1 = bias[col0 + 1];
            *(float2*)(Cf + (size_t)row0 * QD + col0) =
                make_float2(acc[i][j][0] + b0, acc[i][j][1] + b1);
            *(float2*)(Cf + (size_t)(row0 + 8) * QD + col0) =
                make_float2(acc[i][j][2] + b0, acc[i][j][3] + b1);
        }
    }
}

// ---------------------------------------------------------------------------
// Fused attention (exact R14 version with max-subtraction, validated).
// ---------------------------------------------------------------------------
#define AT_Q    0
#define AT_K    16384
#define AT_BOX  26624
#define AT_RED  67584
#define AT_MASK 69632
#define AT_V    0
#define AT_P    16384
#define AT_SMEM 69952

__global__ void __launch_bounds__(128, 3)
attn_fused(const __half* __restrict__ q, const __half* __restrict__ kp,
           const __half* __restrict__ vt,
           const int* __restrict__ mask, const float* __restrict__ box,
           __half* __restrict__ ao)
{
    extern __shared__ char smem[];
    const uint32_t sbase = smem_u32(smem);
    const int tid  = threadIdx.x;
    const int wid  = tid >> 5;
    const int lane = tid & 31;
    const int wr   = wid >> 1;
    const int wc   = wid & 1;
    const int bh   = blockIdx.y;
    const int b    = bh >> 3, h = bh & 7;
    const int nbase = blockIdx.x * 128;

    int* smask = (int*)(smem + AT_MASK);
    if (tid < M_SZ) smask[tid] = mask[b * M_SZ + tid];

#pragma unroll
    for (int u = 0; u < 8; u++) {
        const int task = u * 128 + tid;
        const int row  = task >> 3, ch = task & 7;
        cp_async16(sbase + AT_Q + SWZ(row * 128 + ch * 16),
                   q + (size_t)(b * N_SZ + nbase + row) * INNER + h * CDIM + ch * 8, 16);
    }
#pragma unroll
    for (int u = 0; u < 5; u++) {
        const int task = u * 128 + tid;
        const int row  = task >> 3, ch = task & 7;
        cp_async16(sbase + AT_K + SWZ(row * 128 + ch * 16),
                   kp + (size_t)(b * M_SZ + row) * INNER + h * CDIM + ch * 8, 16);
    }
#pragma unroll
    for (int u = 0; u < 20; u++) {
        const int task = u * 128 + tid;
        const int row  = task / 20, ch = task - row * 20;
        cp_async16(sbase + AT_BOX + row * 320 + ch * 16,
                   box + (size_t)(b * N_SZ + nbase + row) * M_SZ + ch * 4, 16);
    }
    cp_commit();
    cp_wait<0>();
    __syncthreads();

    const int g  = lane >> 3;
    const int r8 = lane & 7;
    const int a_row_off = (g & 1) * 8 + r8;
    const int a_k_off   = (g >> 1) * 16;

    float acc[4][5][4];
#pragma unroll
    for (int i = 0; i < 4; i++)
#pragma unroll
        for (int j = 0; j < 5; j++)
#pragma unroll
            for (int e = 0; e < 4; e++) acc[i][j][e] = 0.0f;

#pragma unroll
    for (int ks = 0; ks < 4; ks++) {
        uint32_t af[4][4], bf[5][2];
#pragma unroll
        for (int i = 0; i < 4; i++)
            ldmatrix_x4(af[i], sbase + AT_Q + SWZ((wr * 64 + i * 16 + a_row_off) * 128
                                                  + ks * 32 + a_k_off));
#pragma unroll
        for (int j = 0; j < 5; j++)
            ldmatrix_x2(bf[j], sbase + AT_K + SWZ((wc * 40 + j * 8 + r8) * 128
                                                  + ks * 32 + (g & 1) * 16));
#pragma unroll
        for (int i = 0; i < 4; i++)
#pragma unroll
            for (int j = 0; j < 5; j++)
                mma16816h(acc[i][j], af[i], bf[j]);
    }
    __syncthreads();

#pragma unroll
    for (int u = 0; u < 5; u++) {
        const int task = u * 128 + tid;
        const int row  = task / 10, ch = task - row * 10;
        cp_async16(sbase + AT_V + row * 176 + ch * 16,
                   vt + ((size_t)bh * CDIM + row) * M_SZ + ch * 8, 16);
    }
    cp_commit();

    const float* boxS = (const float*)(smem + AT_BOX);
    const int qrow = lane >> 2;
    const int qcol = (lane & 3) * 2;
#pragma unroll
    for (int i = 0; i < 4; i++)
#pragma unroll
        for (int j = 0; j < 5; j++)
#pragma unroll
            for (int e = 0; e < 4; e++) {
                const int r = wr * 64 + i * 16 + qrow + (e >> 1) * 8;
                const int c = wc * 40 + j * 8 + qcol + (e & 1);
                acc[i][j][e] = smask[c]
                    ? acc[i][j][e] + LAMDA1 * boxS[r * 80 + c] : BIGNEG;
            }

    float* rmax = (float*)(smem + AT_RED);
    float* rsum = rmax + 256;
    float rm[4][2];
#pragma unroll
    for (int i = 0; i < 4; i++)
#pragma unroll
        for (int hf = 0; hf < 2; hf++) {
            float m = BIGNEG;
#pragma unroll
            for (int j = 0; j < 5; j++)
                m = fmaxf(m, fmaxf(acc[i][j][hf * 2], acc[i][j][hf * 2 + 1]));
            m = fmaxf(m, __shfl_xor_sync(0xffffffffu, m, 1));
            m = fmaxf(m, __shfl_xor_sync(0xffffffffu, m, 2));
            rm[i][hf] = m;
        }
    if ((lane & 3) == 0)
#pragma unroll
        for (int i = 0; i < 4; i++)
#pragma unroll
            for (int hf = 0; hf < 2; hf++)
                rmax[wc * 128 + wr * 64 + i * 16 + qrow + hf * 8] = rm[i][hf];
    __syncthreads();

    float rs[4][2];
#pragma unroll
    for (int i = 0; i < 4; i++)
#pragma unroll
        for (int hf = 0; hf < 2; hf++) {
            const int r = wr * 64 + i * 16 + qrow + hf * 8;
            const float m = fmaxf(rmax[r], rmax[128 + r]);
            float s = 0.0f;
#pragma unroll
            for (int j = 0; j < 5; j++) {
                acc[i][j][hf * 2]     = __expf(acc[i][j][hf * 2]     - m);
                acc[i][j][hf * 2 + 1] = __expf(acc[i][j][hf * 2 + 1] - m);
                s += acc[i][j][hf * 2] + acc[i][j][hf * 2 + 1];
            }
            s += __shfl_xor_sync(0xffffffffu, s, 1);
            s += __shfl_xor_sync(0xffffffffu, s, 2);
            rs[i][hf] = s;
        }
    if ((lane & 3) == 0)
#pragma unroll
        for (int i = 0; i < 4; i++)
#pragma unroll
            for (int hf = 0; hf < 2; hf++)
                rsum[wc * 128 + wr * 64 + i * 16 + qrow + hf * 8] = rs[i][hf];
    __syncthreads();

#pragma unroll
    for (int i = 0; i < 4; i++)
#pragma unroll
        for (int hf = 0; hf < 2; hf++) {
            const int r = wr * 64 + i * 16 + qrow + hf * 8;
            const float inv = 1.0f / (rsum[r] + rsum[128 + r]);
#pragma unroll
            for (int j = 0; j < 5; j++) {
                const int c0 = wc * 40 + j * 8 + qcol;
                *(__half2*)(smem + AT_P + r * 176 + c0 * 2) =
                    __floats2half2_rn(acc[i][j][hf * 2] * inv,
                                      acc[i][j][hf * 2 + 1] * inv);
            }
        }
    cp_wait<0>();
    __syncthreads();

    float acc2[4][4][4];
#pragma unroll
    for (int i = 0; i < 4; i++)
#pragma unroll
        for (int j = 0; j < 4; j++)
#pragma unroll
            for (int e = 0; e < 4; e++) acc2[i][j][e] = 0.0f;

#pragma unroll
    for (int ks = 0; ks < 5; ks++) {
        uint32_t af[4][4], bf[4][2];
#pragma unroll
        for (int i = 0; i < 4; i++)
            ldmatrix_x4(af[i], sbase + AT_P + (wr * 64 + i * 16 + a_row_off) * 176
                                  + ks * 32 + a_k_off);
#pragma unroll
        for (int j = 0; j < 4; j++)
            ldmatrix_x2(bf[j], sbase + AT_V + (wc * 32 + j * 8 + r8) * 176
                                  + ks * 32 + (g & 1) * 16);
#pragma unroll
        for (int i = 0; i < 4; i++)
#pragma unroll
            for (int j = 0; j < 4; j++)
                mma16816h(acc2[i][j], af[i], bf[j]);
    }

#pragma unroll
    for (int i = 0; i < 4; i++) {
        const int n0 = nbase + wr * 64 + i * 16 + qrow;
#pragma unroll
        for (int j = 0; j < 4; j++) {
            const int c0 = wc * 32 + j * 8 + qcol;
            const size_t i0 = (size_t)(b * N_SZ + n0) * INNER + h * CDIM + c0;
            *(__half2*)(ao + i0) =
                __floats2half2_rn(acc2[i][j][0], acc2[i][j][1]);
            *(__half2*)(ao + i0 + (size_t)8 * INNER) =
                __floats2half2_rn(acc2[i][j][2], acc2[i][j][3]);
        }
    }
}

// ---------------------------------------------------------------------------
// Launch (4 kernels total)
// ---------------------------------------------------------------------------
extern "C" void kernel_launch(void* const* d_in, const int* in_sizes, int n_in,
                              void* d_out, int out_size)
{
    const float* x    = (const float*)d_in[0];
    const float* key  = (const float*)d_in[1];
    const float* val  = (const float*)d_in[2];
    const int*   mask = (const int*)d_in[3];
    const float* box  = (const float*)d_in[4];
    // d_in[5] road map: softmax-invariant, unused
    const float* Wq   = (const float*)d_in[6];
    const float* Wk   = (const float*)d_in[7];
    const float* Wv   = (const float*)d_in[8];
    const float* Wo   = (const float*)d_in[9];
    const float* bo   = (const float*)d_in[10];
    float*       out  = (float*)d_out;

    __half *xh, *kh, *vh, *wqh, *wkh, *wvh, *woh, *q, *kp, *vt, *ao;
    cudaGetSymbolAddress((void**)&xh, g_xh);
    cudaGetSymbolAddress((void**)&kh, g_kh);
    cudaGetSymbolAddress((void**)&vh, g_vh);
    cudaGetSymbolAddress((void**)&wqh, g_wqh);
    cudaGetSymbolAddress((void**)&wkh, g_wkh);
    cudaGetSymbolAddress((void**)&wvh, g_wvh);
    cudaGetSymbolAddress((void**)&woh, g_woh);
    cudaGetSymbolAddress((void**)&q,  g_q);
    cudaGetSymbolAddress((void**)&kp, g_kp);
    cudaGetSymbolAddress((void**)&vt, g_vt);
    cudaGetSymbolAddress((void**)&ao, g_ao);

    constexpr int SMEM_G = NSTAGE * 2 * STAGE_B;   // 81920
    cudaFuncSetAttribute(gemm_proj, cudaFuncAttributeMaxDynamicSharedMemorySize, SMEM_G);
    cudaFuncSetAttribute(gemm_out,  cudaFuncAttributeMaxDynamicSharedMemorySize, SMEM_G);
    cudaFuncSetAttribute(attn_fused, cudaFuncAttributeMaxDynamicSharedMemorySize, AT_SMEM);

    // 1) all fp32 -> fp16 conversions
    split_all<<<(S7 + 255) / 256, 256>>>(
        x, key, val, Wq, Wk, Wv, Wo, xh, kh, vh, wqh, wkh, wvh, woh);

    // 2) projections, flattened grid — long K/V CTAs first
    gemm_proj<<<dim3(INNER / 128, YTOT), 128, SMEM_G>>>(
        xh, kh, vh, wqh, wkh, wvh, q, kp, vt);

    // 3) fused attention (R14 version)
    attn_fused<<<dim3(N_SZ / 128, B_SZ * HEADS), 128, AT_SMEM>>>(
        q, kp, vt, mask, box, ao);

    // 4) output projection + bias (R14 config)
    gemm_out<<<dim3(ROWS_Q / 128, (QD + 127) / 128), 128, SMEM_G>>>(
        ao, woh, bo, out);
}